// round 2
// baseline (speedup 1.0000x reference)
#include <cuda_runtime.h>

#define BATCH 32
#define SEQ   2048
#define STATE 64
#define LAT   128
#define ENC   256
#define IND   320          // STATE + 2*LAT
#define NPOS  (BATCH*SEQ)  // 65536
#define NCHUNK 32
#define CLEN   64          // SEQ / NCHUNK
#define RPC    8           // batch rows per scan CTA
#define NBS    4           // batch splits (NBS*RPC = BATCH)

// ---------------- scratch (static device globals; no allocation) ----------------
__device__ float g_sum[LAT];
__device__ float g_sumsq[LAT];
__device__ float g_z0[BATCH*LAT];
__device__ float g_h0[BATCH*LAT];
__device__ float g_d[LAT];
__device__ float g_Ap0[LAT*LAT];
__device__ float g_Ap1[LAT*LAT];
__device__ float g_lend[NCHUNK*BATCH*LAT];
__device__ float g_sk[NCHUNK*BATCH*LAT];
__device__ float g_z1[NPOS*LAT];           // 33.5 MB scan outputs

// ---------------- init: zero the BN accumulators ----------------
__global__ void k_init() {
    int t = threadIdx.x;
    if (t < LAT) { g_sum[t] = 0.f; g_sumsq[t] = 0.f; }
}

// ---------------- repeated squaring: builds A^64 in g_Ap1 ----------------
__global__ void k_sq(const float* __restrict__ Aw, int step) {
    const float* src = (step == 0) ? Aw : ((step & 1) ? g_Ap0 : g_Ap1);
    float* dst = (step & 1) ? g_Ap1 : g_Ap0;
    int idx = blockIdx.x * 256 + threadIdx.x;   // 64 blocks * 256 = 16384
    int i = idx >> 7, j = idx & 127;
    float acc = 0.f;
#pragma unroll 8
    for (int k = 0; k < LAT; k++) acc = fmaf(src[i*LAT + k], src[k*LAT + j], acc);
    dst[idx] = acc;
}

// ---------------- encoder: fused 3-layer MLP + BN stats + z0 capture ----------------
__global__ void __launch_bounds__(256) k_enc(
    const float* __restrict__ in,
    const float* __restrict__ w0, const float* __restrict__ b0,
    const float* __restrict__ w1, const float* __restrict__ b1,
    const float* __restrict__ w2, const float* __restrict__ b2)
{
    __shared__ float xs[16][64];
    __shared__ float hA[16][256];
    __shared__ float hB[16][256];
    __shared__ float ssum[LAT], ssq[LAT];
    int t  = threadIdx.x;
    int p0 = blockIdx.x * 16;

    // load x tile [16,64] (float4)
    {
        int i = t >> 4, f = (t & 15) * 4;
        *(float4*)&xs[i][f] = *(const float4*)&in[(long)(p0 + i) * IND + f];
    }
    __syncthreads();

    // L0: hA = relu(x @ w0 + b0), K=64, thread t -> column t
    {
        float acc[16];
#pragma unroll
        for (int i = 0; i < 16; i++) acc[i] = 0.f;
#pragma unroll 4
        for (int k4 = 0; k4 < STATE; k4 += 4) {
            float a0 = w0[(k4+0)*ENC + t], a1 = w0[(k4+1)*ENC + t];
            float a2 = w0[(k4+2)*ENC + t], a3 = w0[(k4+3)*ENC + t];
#pragma unroll
            for (int i = 0; i < 16; i++) {
                float4 x = *(const float4*)&xs[i][k4];
                acc[i] = fmaf(x.x, a0, fmaf(x.y, a1, fmaf(x.z, a2, fmaf(x.w, a3, acc[i]))));
            }
        }
        float bb = b0[t];
#pragma unroll
        for (int i = 0; i < 16; i++) hA[i][t] = fmaxf(acc[i] + bb, 0.f);
    }
    __syncthreads();

    // L1: hB = relu(hA @ w1 + b1), K=256
    {
        float acc[16];
#pragma unroll
        for (int i = 0; i < 16; i++) acc[i] = 0.f;
#pragma unroll 8
        for (int k4 = 0; k4 < ENC; k4 += 4) {
            float a0 = w1[(k4+0)*ENC + t], a1 = w1[(k4+1)*ENC + t];
            float a2 = w1[(k4+2)*ENC + t], a3 = w1[(k4+3)*ENC + t];
#pragma unroll
            for (int i = 0; i < 16; i++) {
                float4 x = *(const float4*)&hA[i][k4];
                acc[i] = fmaf(x.x, a0, fmaf(x.y, a1, fmaf(x.z, a2, fmaf(x.w, a3, acc[i]))));
            }
        }
        float bb = b1[t];
#pragma unroll
        for (int i = 0; i < 16; i++) hB[i][t] = fmaxf(acc[i] + bb, 0.f);
    }
    __syncthreads();
    if (t < LAT) { ssum[t] = 0.f; ssq[t] = 0.f; }
    __syncthreads();

    // L2: z = relu(hB @ w2 + b2), 128 cols; stats + z0 capture
    {
        int j = t & 127, half = t >> 7;
        float acc[8];
#pragma unroll
        for (int r = 0; r < 8; r++) acc[r] = 0.f;
#pragma unroll 8
        for (int k4 = 0; k4 < ENC; k4 += 4) {
            float a0 = w2[(k4+0)*LAT + j], a1 = w2[(k4+1)*LAT + j];
            float a2 = w2[(k4+2)*LAT + j], a3 = w2[(k4+3)*LAT + j];
#pragma unroll
            for (int r = 0; r < 8; r++) {
                int i = half * 8 + r;
                float4 x = *(const float4*)&hB[i][k4];
                acc[r] = fmaf(x.x, a0, fmaf(x.y, a1, fmaf(x.z, a2, fmaf(x.w, a3, acc[r]))));
            }
        }
        float bb = b2[j];
        float ps = 0.f, pq = 0.f, z0v = 0.f;
#pragma unroll
        for (int r = 0; r < 8; r++) {
            float z = fmaxf(acc[r] + bb, 0.f);
            ps += z; pq += z * z;
            if (r == 0) z0v = z;
        }
        atomicAdd(&ssum[j], ps);
        atomicAdd(&ssq[j], pq);
        if (half == 0 && (p0 & (SEQ - 1)) == 0)
            g_z0[(p0 >> 11) * LAT + j] = z0v;   // batch index = p0/SEQ
    }
    __syncthreads();
    if (t < LAT) {
        atomicAdd(&g_sum[t],   ssum[t]);
        atomicAdd(&g_sumsq[t], ssq[t]);
    }
}

// ---------------- finalize: BN params, normalized initial state, clipped diag ----------------
__global__ void k_fin(const float* __restrict__ gamma, const float* __restrict__ beta,
                      const float* __restrict__ Bd)
{
    int j = threadIdx.x;                 // 128 threads
    float inv = 1.f / (float)NPOS;
    float m  = g_sum[j]   * inv;
    float v  = g_sumsq[j] * inv - m * m;
    float rs = rsqrtf(v + 1e-5f);
    float ga = gamma[j], be = beta[j];
    for (int b = 0; b < BATCH; b++) {
        float z = g_z0[b*LAT + j];
        g_h0[b*LAT + j] = (z - m) * rs * ga + be;
    }
    float d = Bd[j];
    g_d[j] = fminf(fmaxf(d, -0.95f), 0.95f);
}

// ---------------- chunked scan pass (pass 0: local zero-init, pass 1: exact + output) ---------
__global__ void __launch_bounds__(128) k_pass(const float* __restrict__ in,
                                              const float* __restrict__ Aw, int pass)
{
    extern __shared__ float sm[];
    float* As = sm;                      // [128][128]
    float* hs = sm + LAT * LAT;          // double buffer [2][RPC][128]
    int j     = threadIdx.x;
    int chunk = blockIdx.x;
    int b0r   = blockIdx.y * RPC;

    for (int idx = j; idx < LAT * LAT; idx += 128) As[idx] = Aw[idx];
    float dj = g_d[j];
#pragma unroll
    for (int i = 0; i < RPC; i++) {
        float v = (pass == 0) ? 0.f : g_sk[(chunk * BATCH + (b0r + i)) * LAT + j];
        hs[i * LAT + j] = v;
    }
    __syncthreads();

    int t0 = chunk * CLEN;
    int buf = 0;
    for (int t = t0; t < t0 + CLEN; t++) {
        float acc[RPC];
#pragma unroll
        for (int i = 0; i < RPC; i++)    // bu_t = u * d
            acc[i] = in[((long)(b0r + i) * SEQ + t) * IND + (STATE + LAT) + j] * dj;

        const float* hb = hs + buf * (RPC * LAT);
#pragma unroll 8
        for (int k4 = 0; k4 < LAT; k4 += 4) {
            float a0 = As[(k4+0)*LAT + j], a1 = As[(k4+1)*LAT + j];
            float a2 = As[(k4+2)*LAT + j], a3 = As[(k4+3)*LAT + j];
#pragma unroll
            for (int i = 0; i < RPC; i++) {
                float4 h = *(const float4*)&hb[i * LAT + k4];
                acc[i] = fmaf(h.x, a0, fmaf(h.y, a1, fmaf(h.z, a2, fmaf(h.w, a3, acc[i]))));
            }
        }
        buf ^= 1;
        float* hn = hs + buf * (RPC * LAT);
#pragma unroll
        for (int i = 0; i < RPC; i++) hn[i * LAT + j] = acc[i];
        if (pass == 1) {
#pragma unroll
            for (int i = 0; i < RPC; i++)
                g_z1[((long)(b0r + i) * SEQ + t) * LAT + j] = acc[i];
        }
        __syncthreads();
    }
    if (pass == 0) {
#pragma unroll
        for (int i = 0; i < RPC; i++)
            g_lend[(chunk * BATCH + (b0r + i)) * LAT + j] = hs[buf * (RPC * LAT) + i * LAT + j];
    }
}

// ---------------- boundary scan: exact chunk-entry states via A^64 ----------------
__global__ void __launch_bounds__(128) k_bound()
{
    extern __shared__ float sm[];
    float* As = sm;                  // A^64
    float* sv = sm + LAT * LAT;      // current state vector
    int j = threadIdx.x;
    int b = blockIdx.x;
    for (int idx = j; idx < LAT * LAT; idx += 128) As[idx] = g_Ap1[idx];
    float s = g_h0[b * LAT + j];
    for (int k = 0; k < NCHUNK; k++) {
        g_sk[(k * BATCH + b) * LAT + j] = s;
        sv[j] = s;
        __syncthreads();
        float acc = g_lend[(k * BATCH + b) * LAT + j];
#pragma unroll 8
        for (int m4 = 0; m4 < LAT; m4 += 4) {
            float a0 = As[(m4+0)*LAT + j], a1 = As[(m4+1)*LAT + j];
            float a2 = As[(m4+2)*LAT + j], a3 = As[(m4+3)*LAT + j];
            float4 h = *(const float4*)&sv[m4];
            acc = fmaf(h.x, a0, fmaf(h.y, a1, fmaf(h.z, a2, fmaf(h.w, a3, acc))));
        }
        __syncthreads();
        s = acc;
    }
}

// ---------------- decoder: fused 3-layer MLP, writes final output ----------------
__global__ void __launch_bounds__(256) k_dec(
    const float* __restrict__ w0, const float* __restrict__ b0,
    const float* __restrict__ w1, const float* __restrict__ b1,
    const float* __restrict__ w2, const float* __restrict__ b2,
    float* __restrict__ out)
{
    __shared__ float zs[16][128];
    __shared__ float hA[16][256];
    __shared__ float hB[16][256];
    int t  = threadIdx.x;
    int p0 = blockIdx.x * 16;

    // load z1 tile [16,128]
#pragma unroll
    for (int q = 0; q < 2; q++) {
        int idx = t + q * 256;                 // 0..511
        int i = idx >> 5, f = (idx & 31) * 4;
        *(float4*)&zs[i][f] = *(const float4*)&g_z1[((long)p0 + i) * LAT + f];
    }
    __syncthreads();

    // L0: hA = relu(z @ w0 + b0), K=128
    {
        float acc[16];
#pragma unroll
        for (int i = 0; i < 16; i++) acc[i] = 0.f;
#pragma unroll 8
        for (int k4 = 0; k4 < LAT; k4 += 4) {
            float a0 = w0[(k4+0)*ENC + t], a1 = w0[(k4+1)*ENC + t];
            float a2 = w0[(k4+2)*ENC + t], a3 = w0[(k4+3)*ENC + t];
#pragma unroll
            for (int i = 0; i < 16; i++) {
                float4 x = *(const float4*)&zs[i][k4];
                acc[i] = fmaf(x.x, a0, fmaf(x.y, a1, fmaf(x.z, a2, fmaf(x.w, a3, acc[i]))));
            }
        }
        float bb = b0[t];
#pragma unroll
        for (int i = 0; i < 16; i++) hA[i][t] = fmaxf(acc[i] + bb, 0.f);
    }
    __syncthreads();

    // L1: hB = relu(hA @ w1 + b1), K=256
    {
        float acc[16];
#pragma unroll
        for (int i = 0; i < 16; i++) acc[i] = 0.f;
#pragma unroll 8
        for (int k4 = 0; k4 < ENC; k4 += 4) {
            float a0 = w1[(k4+0)*ENC + t], a1 = w1[(k4+1)*ENC + t];
            float a2 = w1[(k4+2)*ENC + t], a3 = w1[(k4+3)*ENC + t];
#pragma unroll
            for (int i = 0; i < 16; i++) {
                float4 x = *(const float4*)&hA[i][k4];
                acc[i] = fmaf(x.x, a0, fmaf(x.y, a1, fmaf(x.z, a2, fmaf(x.w, a3, acc[i]))));
            }
        }
        float bb = b1[t];
#pragma unroll
        for (int i = 0; i < 16; i++) hB[i][t] = fmaxf(acc[i] + bb, 0.f);
    }
    __syncthreads();

    // L2: out = hB @ w2 + b2 (no relu), 64 cols, 4 threads per column
    {
        int j = t & 63, qi = t >> 6;         // qi in 0..3, rows qi*4..qi*4+3
        float acc[4];
#pragma unroll
        for (int r = 0; r < 4; r++) acc[r] = 0.f;
#pragma unroll 8
        for (int k4 = 0; k4 < ENC; k4 += 4) {
            float a0 = w2[(k4+0)*STATE + j], a1 = w2[(k4+1)*STATE + j];
            float a2 = w2[(k4+2)*STATE + j], a3 = w2[(k4+3)*STATE + j];
#pragma unroll
            for (int r = 0; r < 4; r++) {
                int i = qi * 4 + r;
                float4 x = *(const float4*)&hB[i][k4];
                acc[r] = fmaf(x.x, a0, fmaf(x.y, a1, fmaf(x.z, a2, fmaf(x.w, a3, acc[r]))));
            }
        }
        float bb = b2[j];
#pragma unroll
        for (int r = 0; r < 4; r++) {
            int i = qi * 4 + r;
            out[(long)(p0 + i) * STATE + j] = acc[r] + bb;
        }
    }
}

// ---------------- launch ----------------
extern "C" void kernel_launch(void* const* d_in, const int* in_sizes, int n_in,
                              void* d_out, int out_size)
{
    const float* in  = (const float*)d_in[0];
    const float* ew0 = (const float*)d_in[1];
    const float* eb0 = (const float*)d_in[2];
    const float* ew1 = (const float*)d_in[3];
    const float* eb1 = (const float*)d_in[4];
    const float* ew2 = (const float*)d_in[5];
    const float* eb2 = (const float*)d_in[6];
    const float* gam = (const float*)d_in[7];
    const float* bet = (const float*)d_in[8];
    const float* Aw  = (const float*)d_in[9];
    const float* Bd  = (const float*)d_in[10];
    const float* dw0 = (const float*)d_in[11];
    const float* db0 = (const float*)d_in[12];
    const float* dw1 = (const float*)d_in[13];
    const float* db1 = (const float*)d_in[14];
    const float* dw2 = (const float*)d_in[15];
    const float* db2 = (const float*)d_in[16];
    float* out = (float*)d_out;

    cudaFuncSetAttribute(k_pass,  cudaFuncAttributeMaxDynamicSharedMemorySize, 73728);
    cudaFuncSetAttribute(k_bound, cudaFuncAttributeMaxDynamicSharedMemorySize, 66560);

    k_init<<<1, 128>>>();
    for (int s = 0; s < 6; s++) k_sq<<<64, 256>>>(Aw, s);          // A^64 -> g_Ap1
    k_enc<<<NPOS / 16, 256>>>(in, ew0, eb0, ew1, eb1, ew2, eb2);
    k_fin<<<1, 128>>>(gam, bet, Bd);
    k_pass<<<dim3(NCHUNK, NBS), 128, 73728>>>(in, Aw, 0);          // local scans
    k_bound<<<BATCH, 128, 66560>>>();                              // chunk-entry states
    k_pass<<<dim3(NCHUNK, NBS), 128, 73728>>>(in, Aw, 1);          // exact scan -> g_z1
    k_dec<<<NPOS / 16, 256>>>(dw0, db0, dw1, db1, dw2, db2, out);
}